// round 7
// baseline (speedup 1.0000x reference)
#include <cuda_runtime.h>
#include <cstdint>

#define NSAMP 65536      // 2*B halves
#define BORIG 32768
#define TT    15

typedef unsigned long long u64;

// Scratch (all sample-minor / coalesced).
__device__ u64   g_xT[(size_t)30 * NSAMP];                 // transposed input pairs
__device__ u64   g_l0u[(size_t)2 * TT * 32 * NSAMP];       // layer-0 output feature-pairs (~503 MB)
__device__ float g_last[(size_t)2 * 64 * NSAMP];           // final states (~33 MB)

// ---- packed f32x2 helpers ----
__device__ __forceinline__ u64 pack2(float lo, float hi) {
    u64 r;
    asm("mov.b64 %0, {%1, %2};" : "=l"(r) : "r"(__float_as_uint(lo)), "r"(__float_as_uint(hi)));
    return r;
}
__device__ __forceinline__ void unpack2(u64 a, float& lo, float& hi) {
    unsigned x, y;
    asm("mov.b64 {%0, %1}, %2;" : "=r"(x), "=r"(y) : "l"(a));
    lo = __uint_as_float(x); hi = __uint_as_float(y);
}
__device__ __forceinline__ void fma2(u64& d, u64 a, u64 b) {
    asm("fma.rn.f32x2 %0, %1, %2, %0;" : "+l"(d) : "l"(a), "l"(b));
}
__device__ __forceinline__ float usum(u64 a) {
    float lo, hi; unpack2(a, lo, hi); return lo + hi;
}

// ---- fast activations: single-MUFU tanh; sigmoid via tanh identity ----
__device__ __forceinline__ float tanhx(float x) {
    float r;
    asm("tanh.approx.f32 %0, %1;" : "=f"(r) : "f"(x));
    return r;
}
__device__ __forceinline__ float sigf(float x) {
    return fmaf(0.5f, tanhx(0.5f * x), 0.5f);
}

// ---------------- Input transpose: pos -> g_xT[(t*2+p)][sample] (u64 pairs) ----------------
__global__ void __launch_bounds__(128) k_transpose(const float* __restrict__ pos)
{
    __shared__ float sx[128 * 60];
    const unsigned s0 = blockIdx.x * 128u;
    for (int idx = threadIdx.x; idx < 128 * 60; idx += 128) {
        int i = idx / 60, f = idx % 60;
        unsigned s = s0 + i;
        sx[idx] = pos[s < BORIG ? (size_t)s * 120 + f : (size_t)(s - BORIG) * 120 + 60 + f];
    }
    __syncthreads();
    const int i = threadIdx.x;
    const unsigned s = s0 + i;
#pragma unroll
    for (int u = 0; u < 30; ++u) {
        int t = u >> 1, p = u & 1;
        g_xT[(size_t)u * NSAMP + s] = pack2(sx[i * 60 + t * 4 + p * 2],
                                            sx[i * 60 + t * 4 + p * 2 + 1]);
    }
}

// ---------------- Layer 0: D=4 input, N=4 samples/thread ----------------
__global__ void __launch_bounds__(128) lstm_layer0(
    const float* __restrict__ lWih, const float* __restrict__ lWhh, const float* __restrict__ lb,
    const float* __restrict__ vWih, const float* __restrict__ vWhh, const float* __restrict__ vb)
{
    __shared__ __align__(16) float sWf[128 * 36];
    __shared__ float sB[128];
    const int d  = blockIdx.y;
    const int br = blockIdx.z;
    const float* Wih = (br ? vWih : lWih) + d * 128 * 4;
    const float* Whh = (br ? vWhh : lWhh) + d * 128 * 32;
    const float* bb  = (br ? vb   : lb  ) + d * 128;

    for (int idx = threadIdx.x; idx < 128 * 36; idx += 128) {
        int r = idx / 36, o = idx % 36;
        sWf[idx] = (o < 4) ? Wih[r * 4 + o] : Whh[r * 32 + (o - 4)];
    }
    sB[threadIdx.x] = bb[threadIdx.x];
    __syncthreads();

    const u64* sW = reinterpret_cast<const u64*>(sWf);
    const unsigned s0 = blockIdx.x * 512u + threadIdx.x;   // samples s0 + n*128

    u64 v2[4][18];                 // [0,1]=x pairs, [2..17]=h pairs
    float c[4][32], hn[4][32];
#pragma unroll
    for (int n = 0; n < 4; ++n)
#pragma unroll
        for (int k = 2; k < 18; ++k) v2[n][k] = 0;
#pragma unroll 1
    for (int j = 0; j < 32; ++j)
#pragma unroll
        for (int n = 0; n < 4; ++n) c[n][j] = 0.f;

    for (int step = 0; step < TT; ++step) {
        const int t = d ? (TT - 1 - step) : step;
#pragma unroll
        for (int n = 0; n < 4; ++n) {
            v2[n][0] = g_xT[(size_t)(t * 2    ) * NSAMP + s0 + n * 128];
            v2[n][1] = g_xT[(size_t)(t * 2 + 1) * NSAMP + s0 + n * 128];
        }

#pragma unroll 1
        for (int j = 0; j < 32; ++j) {
            u64 acc[4][4];
#pragma unroll
            for (int g = 0; g < 4; ++g)
#pragma unroll
                for (int n = 0; n < 4; ++n) acc[g][n] = 0;
#pragma unroll
            for (int g = 0; g < 4; ++g) {
                const ulonglong2* row = reinterpret_cast<const ulonglong2*>(sW + (size_t)(j + 32 * g) * 18);
#pragma unroll
                for (int k2 = 0; k2 < 9; ++k2) {
                    ulonglong2 w = row[k2];
#pragma unroll
                    for (int n = 0; n < 4; ++n) {
                        fma2(acc[g][n], w.x, v2[n][2 * k2]);
                        fma2(acc[g][n], w.y, v2[n][2 * k2 + 1]);
                    }
                }
            }
            float bi = sB[j], bf = sB[j + 32], bg = sB[j + 64], bo = sB[j + 96];
#pragma unroll
            for (int n = 0; n < 4; ++n) {
                float iv = usum(acc[0][n]) + bi;
                float fv = usum(acc[1][n]) + bf;
                float gv = usum(acc[2][n]) + bg;
                float ov = usum(acc[3][n]) + bo;
                float cn = sigf(fv) * c[n][j] + sigf(iv) * tanhx(gv);
                c[n][j] = cn;
                hn[n][j] = sigf(ov) * tanhx(cn);
            }
        }

        u64* gb = g_l0u + ((size_t)(br * TT + t) * 32 + d * 16) * NSAMP;
#pragma unroll
        for (int q = 0; q < 16; ++q) {
#pragma unroll
            for (int n = 0; n < 4; ++n) {
                u64 hp = pack2(hn[n][2 * q], hn[n][2 * q + 1]);
                v2[n][2 + q] = hp;
                gb[(size_t)q * NSAMP + s0 + n * 128] = hp;
            }
        }
    }
}

// ---------------- Layer 1: N=2 samples/thread; fwd 15 steps + bwd single step --------
template<int NKP>
__device__ __forceinline__ void cell1(const u64* __restrict__ sW, const float* __restrict__ sB,
                                      const u64* vA, const u64* vB,
                                      float* cA, float* cB, float* hA, float* hB)
{
#pragma unroll 2
    for (int j = 0; j < 32; ++j) {
        u64 aA[4], aB[4];
#pragma unroll
        for (int g = 0; g < 4; ++g) { aA[g] = 0; aB[g] = 0; }
#pragma unroll
        for (int g = 0; g < 4; ++g) {
            const ulonglong2* row = reinterpret_cast<const ulonglong2*>(sW + (size_t)(j + 32 * g) * NKP);
#pragma unroll
            for (int k2 = 0; k2 < NKP / 2; ++k2) {
                ulonglong2 w = row[k2];
                fma2(aA[g], w.x, vA[2 * k2]); fma2(aA[g], w.y, vA[2 * k2 + 1]);
                fma2(aB[g], w.x, vB[2 * k2]); fma2(aB[g], w.y, vB[2 * k2 + 1]);
            }
        }
        float bi = sB[j], bf = sB[j + 32], bg = sB[j + 64], bo = sB[j + 96];
        {
            float iv = usum(aA[0]) + bi, fv = usum(aA[1]) + bf;
            float gv = usum(aA[2]) + bg, ov = usum(aA[3]) + bo;
            float cn = sigf(fv) * cA[j] + sigf(iv) * tanhx(gv);
            cA[j] = cn; hA[j] = sigf(ov) * tanhx(cn);
        }
        {
            float iv = usum(aB[0]) + bi, fv = usum(aB[1]) + bf;
            float gv = usum(aB[2]) + bg, ov = usum(aB[3]) + bo;
            float cn = sigf(fv) * cB[j] + sigf(iv) * tanhx(gv);
            cB[j] = cn; hB[j] = sigf(ov) * tanhx(cn);
        }
    }
}

__global__ void __launch_bounds__(128) lstm_layer1(
    const float* __restrict__ lWih, const float* __restrict__ lWhh, const float* __restrict__ lb,
    const float* __restrict__ vWih, const float* __restrict__ vWhh, const float* __restrict__ vb)
{
    extern __shared__ __align__(16) float sm1[];
    float* sWFf = sm1;                       // 128*96
    float* sWBf = sm1 + 128 * 96;            // 128*64
    float* sBF  = sWBf + 128 * 64;           // 128
    float* sBB  = sBF + 128;                 // 128
    const int br = blockIdx.y;
    const float* Wih = br ? vWih : lWih;
    const float* Whh = br ? vWhh : lWhh;
    const float* bb  = br ? vb   : lb;

    for (int idx = threadIdx.x; idx < 128 * 96; idx += 128) {
        int r = idx / 96, o = idx % 96;
        sWFf[idx] = (o < 64) ? Wih[r * 64 + o] : Whh[r * 32 + (o - 64)];
    }
    for (int idx = threadIdx.x; idx < 128 * 64; idx += 128) {
        int r = idx / 64, o = idx % 64;
        sWBf[idx] = Wih[128 * 64 + r * 64 + o];       // dir 1
    }
    sBF[threadIdx.x] = bb[threadIdx.x];
    sBB[threadIdx.x] = bb[128 + threadIdx.x];
    __syncthreads();

    const u64* sWF = reinterpret_cast<const u64*>(sWFf);
    const u64* sWB = reinterpret_cast<const u64*>(sWBf);
    const unsigned s = blockIdx.x * 256u + threadIdx.x * 2;   // samples s, s+1

    u64 vA[48], vB[48];
    float cA[32], cB[32], hA[32], hB[32];
#pragma unroll
    for (int k = 32; k < 48; ++k) { vA[k] = 0; vB[k] = 0; }
#pragma unroll 1
    for (int j = 0; j < 32; ++j) { cA[j] = 0.f; cB[j] = 0.f; }

    for (int t = 0; t < TT; ++t) {
        const u64* gb = g_l0u + (size_t)(br * TT + t) * 32 * NSAMP;
#pragma unroll
        for (int kp = 0; kp < 32; ++kp) {
            ulonglong2 xv = *reinterpret_cast<const ulonglong2*>(gb + (size_t)kp * NSAMP + s);
            vA[kp] = xv.x; vB[kp] = xv.y;
        }
        cell1<48>(sWF, sBF, vA, vB, cA, cB, hA, hB);
#pragma unroll
        for (int q = 0; q < 16; ++q) {
            vA[32 + q] = pack2(hA[2 * q], hA[2 * q + 1]);
            vB[32 + q] = pack2(hB[2 * q], hB[2 * q + 1]);
        }
    }

#pragma unroll 1
    for (int j = 0; j < 32; ++j)
        *reinterpret_cast<u64*>(g_last + (size_t)(br * 64 + j) * NSAMP + s) = pack2(hA[j], hB[j]);

    // bwd single step: input = t=14 features (still in vA/vB[0..31]), h0=c0=0
#pragma unroll 1
    for (int j = 0; j < 32; ++j) { cA[j] = 0.f; cB[j] = 0.f; }
    cell1<32>(sWB, sBB, vA, vB, cA, cB, hA, hB);
#pragma unroll 1
    for (int j = 0; j < 32; ++j)
        *reinterpret_cast<u64*>(g_last + (size_t)(br * 64 + 32 + j) * NSAMP + s) = pack2(hA[j], hB[j]);
}

// ---------------- Head: argmax masks + FC (full MLP) ----------------
__global__ void __launch_bounds__(128) head_kernel(
    const float* __restrict__ dir,
    const float* __restrict__ lW, const float* __restrict__ lbias,
    const float* __restrict__ vW, const float* __restrict__ vbias,
    float* __restrict__ out)
{
    const int b = blockIdx.x * 128 + threadIdx.x;
    if (b >= BORIG) return;

    const float* di = dir + (size_t)b * 6;
    int am = 0; float mv = di[0];
#pragma unroll
    for (int i = 1; i < 6; ++i) { float x = di[i]; if (x > mv) { mv = x; am = i; } }
    const float m_vor = (am == 1 || am == 4) ? 1.f : 0.f;
    const float m_r   = (am == 0 || am == 5) ? 1.f : 0.f;
    const float m_l   = (am == 2 || am == 3) ? 1.f : 0.f;

    const float* ll = g_last + b;                              // lvl, left half
    const float* lr = g_last + b + BORIG;                      // lvl, right half
    const float* vl = g_last + (size_t)64 * NSAMP + b;         // vor, left
    const float* vr = g_last + (size_t)64 * NSAMP + b + BORIG; // vor, right

    float xr0 = lbias[0], xr1 = lbias[1], xl0 = lbias[0], xl1 = lbias[1];
#pragma unroll
    for (int k = 0; k < 64; ++k) {
        float w0 = lW[k], w1 = lW[64 + k];
        float a = lr[(size_t)k * NSAMP], bb2 = ll[(size_t)k * NSAMP];
        xr0 = fmaf(a, w0, xr0); xr1 = fmaf(a, w1, xr1);
        xl0 = fmaf(bb2, w0, xl0); xl1 = fmaf(bb2, w1, xl1);
    }
    float xv0 = vbias[0], xv1 = vbias[1];
#pragma unroll
    for (int k = 0; k < 64; ++k) {
        float a = vl[(size_t)k * NSAMP];
        xv0 = fmaf(a, vW[k], xv0); xv1 = fmaf(a, vW[128 + k], xv1);
    }
#pragma unroll
    for (int k = 0; k < 64; ++k) {
        float a = vr[(size_t)k * NSAMP];
        xv0 = fmaf(a, vW[64 + k], xv0); xv1 = fmaf(a, vW[192 + k], xv1);
    }
    out[2 * b]     = xr0 * m_r + xl0 * m_l + xv0 * m_vor;
    out[2 * b + 1] = xr1 * m_r + xl1 * m_l + xv1 * m_vor;
}

extern "C" void kernel_launch(void* const* d_in, const int* in_sizes, int n_in,
                              void* d_out, int out_size)
{
    (void)in_sizes; (void)n_in; (void)out_size;
    const float* dir    = (const float*)d_in[0];
    const float* pos    = (const float*)d_in[1];
    const float* lWih0  = (const float*)d_in[2];
    const float* lWhh0  = (const float*)d_in[3];
    const float* lb0    = (const float*)d_in[4];
    const float* lWih1  = (const float*)d_in[5];
    const float* lWhh1  = (const float*)d_in[6];
    const float* lb1    = (const float*)d_in[7];
    const float* vWih0  = (const float*)d_in[8];
    const float* vWhh0  = (const float*)d_in[9];
    const float* vb0    = (const float*)d_in[10];
    const float* vWih1  = (const float*)d_in[11];
    const float* vWhh1  = (const float*)d_in[12];
    const float* vb1    = (const float*)d_in[13];
    const float* lfcW   = (const float*)d_in[14];
    const float* lfcb   = (const float*)d_in[15];
    const float* vfcW   = (const float*)d_in[16];
    const float* vfcb   = (const float*)d_in[17];
    float* out = (float*)d_out;

    const int smem1 = (128 * 96 + 128 * 64 + 256) * 4;   // 82944 B
    cudaFuncSetAttribute(lstm_layer1, cudaFuncAttributeMaxDynamicSharedMemorySize, smem1);

    k_transpose<<<NSAMP / 128, 128>>>(pos);
    lstm_layer0<<<dim3(NSAMP / 512, 2, 2), 128>>>(lWih0, lWhh0, lb0, vWih0, vWhh0, vb0);
    lstm_layer1<<<dim3(NSAMP / 256, 2), 128, smem1>>>(lWih1, lWhh1, lb1, vWih1, vWhh1, vb1);
    head_kernel<<<256, 128>>>(dir, lfcW, lfcb, vfcW, vfcb, out);
}

// round 8
// speedup vs baseline: 1.0008x; 1.0008x over previous
#include <cuda_runtime.h>
#include <cstdint>

#define NSAMP 65536      // 2*B halves
#define BORIG 32768
#define TT    15

typedef unsigned long long u64;

// Scratch (all sample-minor / coalesced).
__device__ u64   g_xT[(size_t)30 * NSAMP];                 // transposed input pairs
__device__ u64   g_l0u[(size_t)2 * TT * 32 * NSAMP];       // layer-0 output feature-pairs (~503 MB)
__device__ float g_last[(size_t)2 * 64 * NSAMP];           // final states (~33 MB)

// ---- packed f32x2 helpers ----
__device__ __forceinline__ u64 pack2(float lo, float hi) {
    u64 r;
    asm("mov.b64 %0, {%1, %2};" : "=l"(r) : "r"(__float_as_uint(lo)), "r"(__float_as_uint(hi)));
    return r;
}
__device__ __forceinline__ void unpack2(u64 a, float& lo, float& hi) {
    unsigned x, y;
    asm("mov.b64 {%0, %1}, %2;" : "=r"(x), "=r"(y) : "l"(a));
    lo = __uint_as_float(x); hi = __uint_as_float(y);
}
__device__ __forceinline__ void fma2(u64& d, u64 a, u64 b) {
    asm("fma.rn.f32x2 %0, %1, %2, %0;" : "+l"(d) : "l"(a), "l"(b));
}
__device__ __forceinline__ float usum(u64 a) {
    float lo, hi; unpack2(a, lo, hi); return lo + hi;
}

// ---- fast activations: single-MUFU tanh; sigmoid via tanh identity ----
__device__ __forceinline__ float tanhx(float x) {
    float r;
    asm("tanh.approx.f32 %0, %1;" : "=f"(r) : "f"(x));
    return r;
}
__device__ __forceinline__ float sigf(float x) {
    return fmaf(0.5f, tanhx(0.5f * x), 0.5f);
}

// ---------------- Input transpose: pos -> g_xT[(t*2+p)][sample] (u64 pairs) ----------------
__global__ void __launch_bounds__(128) k_transpose(const float* __restrict__ pos)
{
    __shared__ float sx[128 * 60];
    const unsigned s0 = blockIdx.x * 128u;
    for (int idx = threadIdx.x; idx < 128 * 60; idx += 128) {
        int i = idx / 60, f = idx % 60;
        unsigned s = s0 + i;
        sx[idx] = pos[s < BORIG ? (size_t)s * 120 + f : (size_t)(s - BORIG) * 120 + 60 + f];
    }
    __syncthreads();
    const int i = threadIdx.x;
    const unsigned s = s0 + i;
#pragma unroll
    for (int u = 0; u < 30; ++u) {
        int t = u >> 1, p = u & 1;
        g_xT[(size_t)u * NSAMP + s] = pack2(sx[i * 60 + t * 4 + p * 2],
                                            sx[i * 60 + t * 4 + p * 2 + 1]);
    }
}

// ---------------- Layer 0: D=4 input, N=4 samples/thread ----------------
__global__ void __launch_bounds__(128) lstm_layer0(
    const float* __restrict__ lWih, const float* __restrict__ lWhh, const float* __restrict__ lb,
    const float* __restrict__ vWih, const float* __restrict__ vWhh, const float* __restrict__ vb)
{
    __shared__ __align__(16) float sWf[128 * 36];
    __shared__ float sB[128];
    const int d  = blockIdx.y;
    const int br = blockIdx.z;
    const float* Wih = (br ? vWih : lWih) + d * 128 * 4;
    const float* Whh = (br ? vWhh : lWhh) + d * 128 * 32;
    const float* bb  = (br ? vb   : lb  ) + d * 128;

    for (int idx = threadIdx.x; idx < 128 * 36; idx += 128) {
        int r = idx / 36, o = idx % 36;
        sWf[idx] = (o < 4) ? Wih[r * 4 + o] : Whh[r * 32 + (o - 4)];
    }
    sB[threadIdx.x] = bb[threadIdx.x];
    __syncthreads();

    const u64* sW = reinterpret_cast<const u64*>(sWf);
    const unsigned s0 = blockIdx.x * 512u + threadIdx.x;   // samples s0 + n*128

    u64 v2[4][18];                 // [0,1]=x pairs, [2..17]=h pairs
    float c[4][32], hn[4][32];
#pragma unroll
    for (int n = 0; n < 4; ++n)
#pragma unroll
        for (int k = 2; k < 18; ++k) v2[n][k] = 0;
#pragma unroll 1
    for (int j = 0; j < 32; ++j)
#pragma unroll
        for (int n = 0; n < 4; ++n) c[n][j] = 0.f;

    for (int step = 0; step < TT; ++step) {
        const int t = d ? (TT - 1 - step) : step;
#pragma unroll
        for (int n = 0; n < 4; ++n) {
            v2[n][0] = g_xT[(size_t)(t * 2    ) * NSAMP + s0 + n * 128];
            v2[n][1] = g_xT[(size_t)(t * 2 + 1) * NSAMP + s0 + n * 128];
        }

#pragma unroll 1
        for (int j = 0; j < 32; ++j) {
            u64 acc[4][4];
#pragma unroll
            for (int g = 0; g < 4; ++g)
#pragma unroll
                for (int n = 0; n < 4; ++n) acc[g][n] = 0;
#pragma unroll
            for (int g = 0; g < 4; ++g) {
                const ulonglong2* row = reinterpret_cast<const ulonglong2*>(sW + (size_t)(j + 32 * g) * 18);
#pragma unroll
                for (int k2 = 0; k2 < 9; ++k2) {
                    ulonglong2 w = row[k2];
#pragma unroll
                    for (int n = 0; n < 4; ++n) {
                        fma2(acc[g][n], w.x, v2[n][2 * k2]);
                        fma2(acc[g][n], w.y, v2[n][2 * k2 + 1]);
                    }
                }
            }
            float bi = sB[j], bf = sB[j + 32], bg = sB[j + 64], bo = sB[j + 96];
#pragma unroll
            for (int n = 0; n < 4; ++n) {
                float iv = usum(acc[0][n]) + bi;
                float fv = usum(acc[1][n]) + bf;
                float gv = usum(acc[2][n]) + bg;
                float ov = usum(acc[3][n]) + bo;
                float cn = sigf(fv) * c[n][j] + sigf(iv) * tanhx(gv);
                c[n][j] = cn;
                hn[n][j] = sigf(ov) * tanhx(cn);
            }
        }

        u64* gb = g_l0u + ((size_t)(br * TT + t) * 32 + d * 16) * NSAMP;
#pragma unroll
        for (int q = 0; q < 16; ++q) {
#pragma unroll
            for (int n = 0; n < 4; ++n) {
                u64 hp = pack2(hn[n][2 * q], hn[n][2 * q + 1]);
                v2[n][2 + q] = hp;
                gb[(size_t)q * NSAMP + s0 + n * 128] = hp;
            }
        }
    }
}

// ---------------- Layer 1: N=2 samples/thread; fwd 15 steps + bwd single step --------
template<int NKP>
__device__ __forceinline__ void cell1(const u64* __restrict__ sW, const float* __restrict__ sB,
                                      const u64* vA, const u64* vB,
                                      float* cA, float* cB, float* hA, float* hB)
{
#pragma unroll 2
    for (int j = 0; j < 32; ++j) {
        u64 aA[4], aB[4];
#pragma unroll
        for (int g = 0; g < 4; ++g) { aA[g] = 0; aB[g] = 0; }
#pragma unroll
        for (int g = 0; g < 4; ++g) {
            const ulonglong2* row = reinterpret_cast<const ulonglong2*>(sW + (size_t)(j + 32 * g) * NKP);
#pragma unroll
            for (int k2 = 0; k2 < NKP / 2; ++k2) {
                ulonglong2 w = row[k2];
                fma2(aA[g], w.x, vA[2 * k2]); fma2(aA[g], w.y, vA[2 * k2 + 1]);
                fma2(aB[g], w.x, vB[2 * k2]); fma2(aB[g], w.y, vB[2 * k2 + 1]);
            }
        }
        float bi = sB[j], bf = sB[j + 32], bg = sB[j + 64], bo = sB[j + 96];
        {
            float iv = usum(aA[0]) + bi, fv = usum(aA[1]) + bf;
            float gv = usum(aA[2]) + bg, ov = usum(aA[3]) + bo;
            float cn = sigf(fv) * cA[j] + sigf(iv) * tanhx(gv);
            cA[j] = cn; hA[j] = sigf(ov) * tanhx(cn);
        }
        {
            float iv = usum(aB[0]) + bi, fv = usum(aB[1]) + bf;
            float gv = usum(aB[2]) + bg, ov = usum(aB[3]) + bo;
            float cn = sigf(fv) * cB[j] + sigf(iv) * tanhx(gv);
            cB[j] = cn; hB[j] = sigf(ov) * tanhx(cn);
        }
    }
}

__global__ void __launch_bounds__(128) lstm_layer1(
    const float* __restrict__ lWih, const float* __restrict__ lWhh, const float* __restrict__ lb,
    const float* __restrict__ vWih, const float* __restrict__ vWhh, const float* __restrict__ vb)
{
    extern __shared__ __align__(16) float sm1[];
    float* sWFf = sm1;                       // 128*96
    float* sWBf = sm1 + 128 * 96;            // 128*64
    float* sBF  = sWBf + 128 * 64;           // 128
    float* sBB  = sBF + 128;                 // 128
    const int br = blockIdx.y;
    const float* Wih = br ? vWih : lWih;
    const float* Whh = br ? vWhh : lWhh;
    const float* bb  = br ? vb   : lb;

    for (int idx = threadIdx.x; idx < 128 * 96; idx += 128) {
        int r = idx / 96, o = idx % 96;
        sWFf[idx] = (o < 64) ? Wih[r * 64 + o] : Whh[r * 32 + (o - 64)];
    }
    for (int idx = threadIdx.x; idx < 128 * 64; idx += 128) {
        int r = idx / 64, o = idx % 64;
        sWBf[idx] = Wih[128 * 64 + r * 64 + o];       // dir 1
    }
    sBF[threadIdx.x] = bb[threadIdx.x];
    sBB[threadIdx.x] = bb[128 + threadIdx.x];
    __syncthreads();

    const u64* sWF = reinterpret_cast<const u64*>(sWFf);
    const u64* sWB = reinterpret_cast<const u64*>(sWBf);
    const unsigned s = blockIdx.x * 256u + threadIdx.x * 2;   // samples s, s+1

    u64 vA[48], vB[48];
    float cA[32], cB[32], hA[32], hB[32];
#pragma unroll
    for (int k = 32; k < 48; ++k) { vA[k] = 0; vB[k] = 0; }
#pragma unroll 1
    for (int j = 0; j < 32; ++j) { cA[j] = 0.f; cB[j] = 0.f; }

    for (int t = 0; t < TT; ++t) {
        const u64* gb = g_l0u + (size_t)(br * TT + t) * 32 * NSAMP;
#pragma unroll
        for (int kp = 0; kp < 32; ++kp) {
            ulonglong2 xv = *reinterpret_cast<const ulonglong2*>(gb + (size_t)kp * NSAMP + s);
            vA[kp] = xv.x; vB[kp] = xv.y;
        }
        cell1<48>(sWF, sBF, vA, vB, cA, cB, hA, hB);
#pragma unroll
        for (int q = 0; q < 16; ++q) {
            vA[32 + q] = pack2(hA[2 * q], hA[2 * q + 1]);
            vB[32 + q] = pack2(hB[2 * q], hB[2 * q + 1]);
        }
    }

#pragma unroll 1
    for (int j = 0; j < 32; ++j)
        *reinterpret_cast<u64*>(g_last + (size_t)(br * 64 + j) * NSAMP + s) = pack2(hA[j], hB[j]);

    // bwd single step: input = t=14 features (still in vA/vB[0..31]), h0=c0=0
#pragma unroll 1
    for (int j = 0; j < 32; ++j) { cA[j] = 0.f; cB[j] = 0.f; }
    cell1<32>(sWB, sBB, vA, vB, cA, cB, hA, hB);
#pragma unroll 1
    for (int j = 0; j < 32; ++j)
        *reinterpret_cast<u64*>(g_last + (size_t)(br * 64 + 32 + j) * NSAMP + s) = pack2(hA[j], hB[j]);
}

// ---------------- Head: argmax masks + FC (full MLP) ----------------
__global__ void __launch_bounds__(128) head_kernel(
    const float* __restrict__ dir,
    const float* __restrict__ lW, const float* __restrict__ lbias,
    const float* __restrict__ vW, const float* __restrict__ vbias,
    float* __restrict__ out)
{
    const int b = blockIdx.x * 128 + threadIdx.x;
    if (b >= BORIG) return;

    const float* di = dir + (size_t)b * 6;
    int am = 0; float mv = di[0];
#pragma unroll
    for (int i = 1; i < 6; ++i) { float x = di[i]; if (x > mv) { mv = x; am = i; } }
    const float m_vor = (am == 1 || am == 4) ? 1.f : 0.f;
    const float m_r   = (am == 0 || am == 5) ? 1.f : 0.f;
    const float m_l   = (am == 2 || am == 3) ? 1.f : 0.f;

    const float* ll = g_last + b;                              // lvl, left half
    const float* lr = g_last + b + BORIG;                      // lvl, right half
    const float* vl = g_last + (size_t)64 * NSAMP + b;         // vor, left
    const float* vr = g_last + (size_t)64 * NSAMP + b + BORIG; // vor, right

    float xr0 = lbias[0], xr1 = lbias[1], xl0 = lbias[0], xl1 = lbias[1];
#pragma unroll
    for (int k = 0; k < 64; ++k) {
        float w0 = lW[k], w1 = lW[64 + k];
        float a = lr[(size_t)k * NSAMP], bb2 = ll[(size_t)k * NSAMP];
        xr0 = fmaf(a, w0, xr0); xr1 = fmaf(a, w1, xr1);
        xl0 = fmaf(bb2, w0, xl0); xl1 = fmaf(bb2, w1, xl1);
    }
    float xv0 = vbias[0], xv1 = vbias[1];
#pragma unroll
    for (int k = 0; k < 64; ++k) {
        float a = vl[(size_t)k * NSAMP];
        xv0 = fmaf(a, vW[k], xv0); xv1 = fmaf(a, vW[128 + k], xv1);
    }
#pragma unroll
    for (int k = 0; k < 64; ++k) {
        float a = vr[(size_t)k * NSAMP];
        xv0 = fmaf(a, vW[64 + k], xv0); xv1 = fmaf(a, vW[192 + k], xv1);
    }
    out[2 * b]     = xr0 * m_r + xl0 * m_l + xv0 * m_vor;
    out[2 * b + 1] = xr1 * m_r + xl1 * m_l + xv1 * m_vor;
}

extern "C" void kernel_launch(void* const* d_in, const int* in_sizes, int n_in,
                              void* d_out, int out_size)
{
    (void)in_sizes; (void)n_in; (void)out_size;
    const float* dir    = (const float*)d_in[0];
    const float* pos    = (const float*)d_in[1];
    const float* lWih0  = (const float*)d_in[2];
    const float* lWhh0  = (const float*)d_in[3];
    const float* lb0    = (const float*)d_in[4];
    const float* lWih1  = (const float*)d_in[5];
    const float* lWhh1  = (const float*)d_in[6];
    const float* lb1    = (const float*)d_in[7];
    const float* vWih0  = (const float*)d_in[8];
    const float* vWhh0  = (const float*)d_in[9];
    const float* vb0    = (const float*)d_in[10];
    const float* vWih1  = (const float*)d_in[11];
    const float* vWhh1  = (const float*)d_in[12];
    const float* vb1    = (const float*)d_in[13];
    const float* lfcW   = (const float*)d_in[14];
    const float* lfcb   = (const float*)d_in[15];
    const float* vfcW   = (const float*)d_in[16];
    const float* vfcb   = (const float*)d_in[17];
    float* out = (float*)d_out;

    const int smem1 = (128 * 96 + 128 * 64 + 256) * 4;   // 82944 B
    cudaFuncSetAttribute(lstm_layer1, cudaFuncAttributeMaxDynamicSharedMemorySize, smem1);

    k_transpose<<<NSAMP / 128, 128>>>(pos);
    lstm_layer0<<<dim3(NSAMP / 512, 2, 2), 128>>>(lWih0, lWhh0, lb0, vWih0, vWhh0, vb0);
    lstm_layer1<<<dim3(NSAMP / 256, 2), 128, smem1>>>(lWih1, lWhh1, lb1, vWih1, vWhh1, vb1);
    head_kernel<<<256, 128>>>(dir, lfcW, lfcb, vfcW, vfcb, out);
}

// round 9
// speedup vs baseline: 1.0010x; 1.0003x over previous
#include <cuda_runtime.h>
#include <cstdint>

#define NSAMP 65536      // 2*B halves
#define BORIG 32768
#define TT    15

typedef unsigned long long u64;

// Scratch (all sample-minor / coalesced).
__device__ u64   g_xT[(size_t)30 * NSAMP];                 // transposed input pairs
__device__ u64   g_l0u[(size_t)2 * TT * 32 * NSAMP];       // layer-0 output feature-pairs (~503 MB)
__device__ float g_last[(size_t)2 * 64 * NSAMP];           // final states (~33 MB)

// ---- packed f32x2 helpers ----
__device__ __forceinline__ u64 pack2(float lo, float hi) {
    u64 r;
    asm("mov.b64 %0, {%1, %2};" : "=l"(r) : "r"(__float_as_uint(lo)), "r"(__float_as_uint(hi)));
    return r;
}
__device__ __forceinline__ void unpack2(u64 a, float& lo, float& hi) {
    unsigned x, y;
    asm("mov.b64 {%0, %1}, %2;" : "=r"(x), "=r"(y) : "l"(a));
    lo = __uint_as_float(x); hi = __uint_as_float(y);
}
__device__ __forceinline__ void fma2(u64& d, u64 a, u64 b) {
    asm("fma.rn.f32x2 %0, %1, %2, %0;" : "+l"(d) : "l"(a), "l"(b));
}
__device__ __forceinline__ float usum(u64 a) {
    float lo, hi; unpack2(a, lo, hi); return lo + hi;
}

// ---- fast activations: single-MUFU tanh; sigmoid via tanh identity ----
__device__ __forceinline__ float tanhx(float x) {
    float r;
    asm("tanh.approx.f32 %0, %1;" : "=f"(r) : "f"(x));
    return r;
}
__device__ __forceinline__ float sigf(float x) {
    return fmaf(0.5f, tanhx(0.5f * x), 0.5f);
}

// ---------------- Input transpose: pos -> g_xT[(t*2+p)][sample] (u64 pairs) ----------------
__global__ void __launch_bounds__(128) k_transpose(const float* __restrict__ pos)
{
    __shared__ float sx[128 * 60];
    const unsigned s0 = blockIdx.x * 128u;
    for (int idx = threadIdx.x; idx < 128 * 60; idx += 128) {
        int i = idx / 60, f = idx % 60;
        unsigned s = s0 + i;
        sx[idx] = pos[s < BORIG ? (size_t)s * 120 + f : (size_t)(s - BORIG) * 120 + 60 + f];
    }
    __syncthreads();
    const int i = threadIdx.x;
    const unsigned s = s0 + i;
#pragma unroll
    for (int u = 0; u < 30; ++u) {
        int t = u >> 1, p = u & 1;
        g_xT[(size_t)u * NSAMP + s] = pack2(sx[i * 60 + t * 4 + p * 2],
                                            sx[i * 60 + t * 4 + p * 2 + 1]);
    }
}

// ---------------- Layer 0: D=4 input, N=4 samples/thread ----------------
__global__ void __launch_bounds__(128) lstm_layer0(
    const float* __restrict__ lWih, const float* __restrict__ lWhh, const float* __restrict__ lb,
    const float* __restrict__ vWih, const float* __restrict__ vWhh, const float* __restrict__ vb)
{
    __shared__ __align__(16) float sWf[128 * 36];
    __shared__ float sB[128];
    const int d  = blockIdx.y;
    const int br = blockIdx.z;
    const float* Wih = (br ? vWih : lWih) + d * 128 * 4;
    const float* Whh = (br ? vWhh : lWhh) + d * 128 * 32;
    const float* bb  = (br ? vb   : lb  ) + d * 128;

    for (int idx = threadIdx.x; idx < 128 * 36; idx += 128) {
        int r = idx / 36, o = idx % 36;
        sWf[idx] = (o < 4) ? Wih[r * 4 + o] : Whh[r * 32 + (o - 4)];
    }
    sB[threadIdx.x] = bb[threadIdx.x];
    __syncthreads();

    const u64* sW = reinterpret_cast<const u64*>(sWf);
    const unsigned s0 = blockIdx.x * 512u + threadIdx.x;   // samples s0 + n*128

    u64 v2[4][18];                 // [0,1]=x pairs, [2..17]=h pairs
    float c[4][32], hn[4][32];
#pragma unroll
    for (int n = 0; n < 4; ++n)
#pragma unroll
        for (int k = 2; k < 18; ++k) v2[n][k] = 0;
#pragma unroll 1
    for (int j = 0; j < 32; ++j)
#pragma unroll
        for (int n = 0; n < 4; ++n) c[n][j] = 0.f;

    for (int step = 0; step < TT; ++step) {
        const int t = d ? (TT - 1 - step) : step;
#pragma unroll
        for (int n = 0; n < 4; ++n) {
            v2[n][0] = g_xT[(size_t)(t * 2    ) * NSAMP + s0 + n * 128];
            v2[n][1] = g_xT[(size_t)(t * 2 + 1) * NSAMP + s0 + n * 128];
        }

#pragma unroll 1
        for (int j = 0; j < 32; ++j) {
            u64 acc[4][4];
#pragma unroll
            for (int g = 0; g < 4; ++g)
#pragma unroll
                for (int n = 0; n < 4; ++n) acc[g][n] = 0;
#pragma unroll
            for (int g = 0; g < 4; ++g) {
                const ulonglong2* row = reinterpret_cast<const ulonglong2*>(sW + (size_t)(j + 32 * g) * 18);
#pragma unroll
                for (int k2 = 0; k2 < 9; ++k2) {
                    ulonglong2 w = row[k2];
#pragma unroll
                    for (int n = 0; n < 4; ++n) {
                        fma2(acc[g][n], w.x, v2[n][2 * k2]);
                        fma2(acc[g][n], w.y, v2[n][2 * k2 + 1]);
                    }
                }
            }
            float bi = sB[j], bf = sB[j + 32], bg = sB[j + 64], bo = sB[j + 96];
#pragma unroll
            for (int n = 0; n < 4; ++n) {
                float iv = usum(acc[0][n]) + bi;
                float fv = usum(acc[1][n]) + bf;
                float gv = usum(acc[2][n]) + bg;
                float ov = usum(acc[3][n]) + bo;
                float cn = sigf(fv) * c[n][j] + sigf(iv) * tanhx(gv);
                c[n][j] = cn;
                hn[n][j] = sigf(ov) * tanhx(cn);
            }
        }

        u64* gb = g_l0u + ((size_t)(br * TT + t) * 32 + d * 16) * NSAMP;
#pragma unroll
        for (int q = 0; q < 16; ++q) {
#pragma unroll
            for (int n = 0; n < 4; ++n) {
                u64 hp = pack2(hn[n][2 * q], hn[n][2 * q + 1]);
                v2[n][2 + q] = hp;
                gb[(size_t)q * NSAMP + s0 + n * 128] = hp;
            }
        }
    }
}

// ---------------- Layer 1: N=2 samples/thread; fwd 15 steps + bwd single step --------
template<int NKP>
__device__ __forceinline__ void cell1(const u64* __restrict__ sW, const float* __restrict__ sB,
                                      const u64* vA, const u64* vB,
                                      float* cA, float* cB, float* hA, float* hB)
{
#pragma unroll 2
    for (int j = 0; j < 32; ++j) {
        u64 aA[4], aB[4];
#pragma unroll
        for (int g = 0; g < 4; ++g) { aA[g] = 0; aB[g] = 0; }
#pragma unroll
        for (int g = 0; g < 4; ++g) {
            const ulonglong2* row = reinterpret_cast<const ulonglong2*>(sW + (size_t)(j + 32 * g) * NKP);
#pragma unroll
            for (int k2 = 0; k2 < NKP / 2; ++k2) {
                ulonglong2 w = row[k2];
                fma2(aA[g], w.x, vA[2 * k2]); fma2(aA[g], w.y, vA[2 * k2 + 1]);
                fma2(aB[g], w.x, vB[2 * k2]); fma2(aB[g], w.y, vB[2 * k2 + 1]);
            }
        }
        float bi = sB[j], bf = sB[j + 32], bg = sB[j + 64], bo = sB[j + 96];
        {
            float iv = usum(aA[0]) + bi, fv = usum(aA[1]) + bf;
            float gv = usum(aA[2]) + bg, ov = usum(aA[3]) + bo;
            float cn = sigf(fv) * cA[j] + sigf(iv) * tanhx(gv);
            cA[j] = cn; hA[j] = sigf(ov) * tanhx(cn);
        }
        {
            float iv = usum(aB[0]) + bi, fv = usum(aB[1]) + bf;
            float gv = usum(aB[2]) + bg, ov = usum(aB[3]) + bo;
            float cn = sigf(fv) * cB[j] + sigf(iv) * tanhx(gv);
            cB[j] = cn; hB[j] = sigf(ov) * tanhx(cn);
        }
    }
}

__global__ void __launch_bounds__(128) lstm_layer1(
    const float* __restrict__ lWih, const float* __restrict__ lWhh, const float* __restrict__ lb,
    const float* __restrict__ vWih, const float* __restrict__ vWhh, const float* __restrict__ vb)
{
    extern __shared__ __align__(16) float sm1[];
    float* sWFf = sm1;                       // 128*96
    float* sWBf = sm1 + 128 * 96;            // 128*64
    float* sBF  = sWBf + 128 * 64;           // 128
    float* sBB  = sBF + 128;                 // 128
    const int br = blockIdx.y;
    const float* Wih = br ? vWih : lWih;
    const float* Whh = br ? vWhh : lWhh;
    const float* bb  = br ? vb   : lb;

    for (int idx = threadIdx.x; idx < 128 * 96; idx += 128) {
        int r = idx / 96, o = idx % 96;
        sWFf[idx] = (o < 64) ? Wih[r * 64 + o] : Whh[r * 32 + (o - 64)];
    }
    for (int idx = threadIdx.x; idx < 128 * 64; idx += 128) {
        int r = idx / 64, o = idx % 64;
        sWBf[idx] = Wih[128 * 64 + r * 64 + o];       // dir 1
    }
    sBF[threadIdx.x] = bb[threadIdx.x];
    sBB[threadIdx.x] = bb[128 + threadIdx.x];
    __syncthreads();

    const u64* sWF = reinterpret_cast<const u64*>(sWFf);
    const u64* sWB = reinterpret_cast<const u64*>(sWBf);
    const unsigned s = blockIdx.x * 256u + threadIdx.x * 2;   // samples s, s+1

    u64 vA[48], vB[48];
    float cA[32], cB[32], hA[32], hB[32];
#pragma unroll
    for (int k = 32; k < 48; ++k) { vA[k] = 0; vB[k] = 0; }
#pragma unroll 1
    for (int j = 0; j < 32; ++j) { cA[j] = 0.f; cB[j] = 0.f; }

    for (int t = 0; t < TT; ++t) {
        const u64* gb = g_l0u + (size_t)(br * TT + t) * 32 * NSAMP;
#pragma unroll
        for (int kp = 0; kp < 32; ++kp) {
            ulonglong2 xv = *reinterpret_cast<const ulonglong2*>(gb + (size_t)kp * NSAMP + s);
            vA[kp] = xv.x; vB[kp] = xv.y;
        }
        cell1<48>(sWF, sBF, vA, vB, cA, cB, hA, hB);
#pragma unroll
        for (int q = 0; q < 16; ++q) {
            vA[32 + q] = pack2(hA[2 * q], hA[2 * q + 1]);
            vB[32 + q] = pack2(hB[2 * q], hB[2 * q + 1]);
        }
    }

#pragma unroll 1
    for (int j = 0; j < 32; ++j)
        *reinterpret_cast<u64*>(g_last + (size_t)(br * 64 + j) * NSAMP + s) = pack2(hA[j], hB[j]);

    // bwd single step: input = t=14 features (still in vA/vB[0..31]), h0=c0=0
#pragma unroll 1
    for (int j = 0; j < 32; ++j) { cA[j] = 0.f; cB[j] = 0.f; }
    cell1<32>(sWB, sBB, vA, vB, cA, cB, hA, hB);
#pragma unroll 1
    for (int j = 0; j < 32; ++j)
        *reinterpret_cast<u64*>(g_last + (size_t)(br * 64 + 32 + j) * NSAMP + s) = pack2(hA[j], hB[j]);
}

// ---------------- Head: argmax masks + FC (full MLP) ----------------
__global__ void __launch_bounds__(128) head_kernel(
    const float* __restrict__ dir,
    const float* __restrict__ lW, const float* __restrict__ lbias,
    const float* __restrict__ vW, const float* __restrict__ vbias,
    float* __restrict__ out)
{
    const int b = blockIdx.x * 128 + threadIdx.x;
    if (b >= BORIG) return;

    const float* di = dir + (size_t)b * 6;
    int am = 0; float mv = di[0];
#pragma unroll
    for (int i = 1; i < 6; ++i) { float x = di[i]; if (x > mv) { mv = x; am = i; } }
    const float m_vor = (am == 1 || am == 4) ? 1.f : 0.f;
    const float m_r   = (am == 0 || am == 5) ? 1.f : 0.f;
    const float m_l   = (am == 2 || am == 3) ? 1.f : 0.f;

    const float* ll = g_last + b;                              // lvl, left half
    const float* lr = g_last + b + BORIG;                      // lvl, right half
    const float* vl = g_last + (size_t)64 * NSAMP + b;         // vor, left
    const float* vr = g_last + (size_t)64 * NSAMP + b + BORIG; // vor, right

    float xr0 = lbias[0], xr1 = lbias[1], xl0 = lbias[0], xl1 = lbias[1];
#pragma unroll
    for (int k = 0; k < 64; ++k) {
        float w0 = lW[k], w1 = lW[64 + k];
        float a = lr[(size_t)k * NSAMP], bb2 = ll[(size_t)k * NSAMP];
        xr0 = fmaf(a, w0, xr0); xr1 = fmaf(a, w1, xr1);
        xl0 = fmaf(bb2, w0, xl0); xl1 = fmaf(bb2, w1, xl1);
    }
    float xv0 = vbias[0], xv1 = vbias[1];
#pragma unroll
    for (int k = 0; k < 64; ++k) {
        float a = vl[(size_t)k * NSAMP];
        xv0 = fmaf(a, vW[k], xv0); xv1 = fmaf(a, vW[128 + k], xv1);
    }
#pragma unroll
    for (int k = 0; k < 64; ++k) {
        float a = vr[(size_t)k * NSAMP];
        xv0 = fmaf(a, vW[64 + k], xv0); xv1 = fmaf(a, vW[192 + k], xv1);
    }
    out[2 * b]     = xr0 * m_r + xl0 * m_l + xv0 * m_vor;
    out[2 * b + 1] = xr1 * m_r + xl1 * m_l + xv1 * m_vor;
}

extern "C" void kernel_launch(void* const* d_in, const int* in_sizes, int n_in,
                              void* d_out, int out_size)
{
    (void)in_sizes; (void)n_in; (void)out_size;
    const float* dir    = (const float*)d_in[0];
    const float* pos    = (const float*)d_in[1];
    const float* lWih0  = (const float*)d_in[2];
    const float* lWhh0  = (const float*)d_in[3];
    const float* lb0    = (const float*)d_in[4];
    const float* lWih1  = (const float*)d_in[5];
    const float* lWhh1  = (const float*)d_in[6];
    const float* lb1    = (const float*)d_in[7];
    const float* vWih0  = (const float*)d_in[8];
    const float* vWhh0  = (const float*)d_in[9];
    const float* vb0    = (const float*)d_in[10];
    const float* vWih1  = (const float*)d_in[11];
    const float* vWhh1  = (const float*)d_in[12];
    const float* vb1    = (const float*)d_in[13];
    const float* lfcW   = (const float*)d_in[14];
    const float* lfcb   = (const float*)d_in[15];
    const float* vfcW   = (const float*)d_in[16];
    const float* vfcb   = (const float*)d_in[17];
    float* out = (float*)d_out;

    const int smem1 = (128 * 96 + 128 * 64 + 256) * 4;   // 82944 B
    cudaFuncSetAttribute(lstm_layer1, cudaFuncAttributeMaxDynamicSharedMemorySize, smem1);

    k_transpose<<<NSAMP / 128, 128>>>(pos);
    lstm_layer0<<<dim3(NSAMP / 512, 2, 2), 128>>>(lWih0, lWhh0, lb0, vWih0, vWhh0, vb0);
    lstm_layer1<<<dim3(NSAMP / 256, 2), 128, smem1>>>(lWih1, lWhh1, lb1, vWih1, vWhh1, vb1);
    head_kernel<<<256, 128>>>(dir, lfcW, lfcb, vfcW, vfcb, out);
}